// round 2
// baseline (speedup 1.0000x reference)
#include <cuda_runtime.h>
#include <cuda_bf16.h>

#define N_NODES 100000
#define N_EDGES 3200000

// Padded positions: one aligned 16B gather per endpoint.
__device__ float4 g_pos4[N_NODES];

// Fused: pad positions into g_pos4 AND zero the accumulator (d_out).
__global__ void prep_kernel(const float* __restrict__ pos,
                            float4* __restrict__ out4, int n) {
    int i = blockIdx.x * blockDim.x + threadIdx.x;
    if (i < n) {
        const float* p = pos + 3 * i;
        float x = p[0], y = p[1], z = p[2];
        g_pos4[i] = make_float4(x, y, z, 0.0f);
        out4[i] = make_float4(0.0f, 0.0f, 0.0f, 0.0f);
    }
}

__device__ __forceinline__ void process_edge(int s, int d, float4* out4) {
    float4 ps = __ldg(&g_pos4[s]);
    float4 pd = __ldg(&g_pos4[d]);
    float rx = pd.x - ps.x;
    float ry = pd.y - ps.y;
    float rz = pd.z - ps.z;
    float dot = fmaf(rx, rx, fmaf(ry, ry, rz * rz));
    // rel==0 -> dot==0 -> inv finite, 0*finite = 0 (matches reference)
    float inv = rsqrtf(fmaxf(dot, 1e-24f));
    float x = rx * inv;
    float y = ry * inv;
    float z = rz * inv;
    float* addr = reinterpret_cast<float*>(out4 + d);
    asm volatile("red.global.add.v4.f32 [%0], {%1, %2, %3, %4};"
                 :: "l"(addr), "f"(1.0f), "f"(x), "f"(y), "f"(z)
                 : "memory");
}

// 4 edges per thread via int4 index loads: coalesced 128-bit index streams.
__global__ void __launch_bounds__(256)
edge_kernel(const int4* __restrict__ src4,
            const int4* __restrict__ dst4,
            float4* __restrict__ out4, int n_quads) {
    int t = blockIdx.x * blockDim.x + threadIdx.x;
    if (t >= n_quads) return;
    int4 s = __ldg(src4 + t);
    int4 d = __ldg(dst4 + t);
    process_edge(s.x, d.x, out4);
    process_edge(s.y, d.y, out4);
    process_edge(s.z, d.z, out4);
    process_edge(s.w, d.w, out4);
}

// 2 nodes per thread, loads batched up-front for MLP=4+.
__global__ void __launch_bounds__(256)
finalize_kernel(const float* __restrict__ node_feat,
                const float* __restrict__ w0,
                const float* __restrict__ w1,
                float4* __restrict__ out4, int n) {
    int i0 = (blockIdx.x * blockDim.x + threadIdx.x) * 2;
    if (i0 >= n) return;
    int i1 = i0 + 1;
    bool has1 = (i1 < n);

    // Batch all loads first (independent -> overlapped).
    float4 a0 = out4[i0];
    float4 a1 = has1 ? out4[i1] : make_float4(0.f, 0.f, 0.f, 0.f);
    float f0 = __ldg(&node_feat[i0]);
    float f1 = has1 ? __ldg(&node_feat[i1]) : 0.0f;
    float w0v = __ldg(&w0[0]);
    float w1x = __ldg(&w1[0]);
    float w1y = __ldg(&w1[1]);
    float w1z = __ldg(&w1[2]);

    {
        float cnt = a0.x;
        float fr = f0 / fmaxf(cnt, 1.0f);
        float4 o;
        o.x = w0v * fr * cnt;
        o.y = w1x * fr * a0.y;
        o.z = w1y * fr * a0.z;
        o.w = w1z * fr * a0.w;
        out4[i0] = o;
    }
    if (has1) {
        float cnt = a1.x;
        float fr = f1 / fmaxf(cnt, 1.0f);
        float4 o;
        o.x = w0v * fr * cnt;
        o.y = w1x * fr * a1.y;
        o.z = w1y * fr * a1.z;
        o.w = w1z * fr * a1.w;
        out4[i1] = o;
    }
}

extern "C" void kernel_launch(void* const* d_in, const int* in_sizes, int n_in,
                              void* d_out, int out_size) {
    const float* positions = (const float*)d_in[0];   // [N,3]
    const float* node_feat = (const float*)d_in[1];   // [N,1]
    const float* w0        = (const float*)d_in[2];   // [1]
    const float* w1        = (const float*)d_in[3];   // [3]
    const int*   edge_src  = (const int*)d_in[4];     // [E]
    const int*   edge_dst  = (const int*)d_in[5];     // [E]

    const int n_nodes = in_sizes[1];
    const int n_edges = in_sizes[4];

    float4* out4 = (float4*)d_out;
    const int B = 256;

    prep_kernel<<<(n_nodes + B - 1) / B, B>>>(positions, out4, n_nodes);

    int n_quads = n_edges / 4;   // E divisible by 4
    edge_kernel<<<(n_quads + B - 1) / B, B>>>((const int4*)edge_src,
                                              (const int4*)edge_dst,
                                              out4, n_quads);

    int n_pairs = (n_nodes + 1) / 2;
    finalize_kernel<<<(n_pairs + B - 1) / B, B>>>(node_feat, w0, w1, out4, n_nodes);
}